// round 15
// baseline (speedup 1.0000x reference)
#include <cuda_runtime.h>
#include <math.h>

#define N_FFT   16384
#define L_SIG   8192
#define D_DIM   1024
#define BSZ     4
#define THREADS 512
#define TW_SIZE (3 * N_FFT / 4)    // extended table: w^k for k < 3N/4

// XOR bank swizzle (Round-4 layout): <=2-way for all strides used here.
#define SWZ(i) ((i) ^ (((i) >> 4) & 15))

__device__ float2 d_tw[TW_SIZE];                     // exp(-2*pi*i*k/N), k < 3N/4
__device__ float4 d_Hf4[(size_t)D_DIM * N_FFT / 2];  // spectra of (h + B*delta0)/N
__device__ unsigned d_flags[D_DIM];

__global__ void init_kernel() {
    int k = blockIdx.x * blockDim.x + threadIdx.x;
    if (k < TW_SIZE) {
        double ang = -2.0 * 3.14159265358979323846 * (double)k / (double)N_FFT;
        d_tw[k] = make_float2((float)cos(ang), (float)sin(ang));
    }
    if (k < D_DIM) d_flags[k] = 0u;
}

__device__ __forceinline__ float2 f2add(float2 a, float2 b) {
    return make_float2(a.x + b.x, a.y + b.y);
}
__device__ __forceinline__ float2 f2sub(float2 a, float2 b) {
    return make_float2(a.x - b.x, a.y - b.y);
}
__device__ __forceinline__ float2 cmul(float2 a, float2 b) {
    return make_float2(a.x * b.x - a.y * b.y, a.x * b.y + a.y * b.x);
}
// multiply by conj(b) — inverse butterflies use the unconjugated table directly
__device__ __forceinline__ float2 cmulc(float2 a, float2 b) {
    return make_float2(a.x * b.x + a.y * b.y, a.y * b.x - a.x * b.y);
}

struct W3 { float2 w1, w2, w3; };
__device__ __forceinline__ W3 loadw(int k) {   // k < N/4
    W3 w;
    w.w1 = d_tw[k];
    w.w2 = d_tw[2 * k];
    w.w3 = d_tw[3 * k];
    return w;
}

// DIF radix-4 butterfly, table twiddles on outputs
__device__ __forceinline__ void dif4w(float2& a0, float2& a1, float2& a2, float2& a3,
                                      const W3& w) {
    float2 t0 = f2add(a0, a2), t1 = f2sub(a0, a2);
    float2 t2 = f2add(a1, a3), t3 = f2sub(a1, a3);
    float2 b0 = f2add(t0, t2), b2 = f2sub(t0, t2);
    float2 b1 = make_float2(t1.x + t3.y, t1.y - t3.x);   // t1 - i*t3
    float2 b3 = make_float2(t1.x - t3.y, t1.y + t3.x);   // t1 + i*t3
    a0 = b0; a1 = cmul(b1, w.w1); a2 = cmul(b2, w.w2); a3 = cmul(b3, w.w3);
}
__device__ __forceinline__ void dif4_nt(float2& a0, float2& a1, float2& a2, float2& a3) {
    float2 t0 = f2add(a0, a2), t1 = f2sub(a0, a2);
    float2 t2 = f2add(a1, a3), t3 = f2sub(a1, a3);
    a0 = f2add(t0, t2);
    a2 = f2sub(t0, t2);
    a1 = make_float2(t1.x + t3.y, t1.y - t3.x);
    a3 = make_float2(t1.x - t3.y, t1.y + t3.x);
}

// DIT radix-4 inverse butterfly, conj-table twiddles (cmulc) on inputs
__device__ __forceinline__ void dit4w(float2& c0, float2& c1, float2& c2, float2& c3,
                                      const W3& w) {
    float2 a1 = cmulc(c1, w.w1), a2 = cmulc(c2, w.w2), a3 = cmulc(c3, w.w3);
    float2 u0 = f2add(c0, a2), u1 = f2sub(c0, a2);
    float2 u2 = f2add(a1, a3), u3 = f2sub(a1, a3);
    c0 = f2add(u0, u2);
    c1 = make_float2(u1.x - u3.y, u1.y + u3.x);  // u1 + i*u3
    c2 = f2sub(u0, u2);
    c3 = make_float2(u1.x + u3.y, u1.y - u3.x);  // u1 - i*u3
}
__device__ __forceinline__ void dit4_nt(float2& c0, float2& c1, float2& c2, float2& c3) {
    float2 u0 = f2add(c0, c2), u1 = f2sub(c0, c2);
    float2 u2 = f2add(c1, c3), u3 = f2sub(c1, c3);
    c0 = f2add(u0, u2);
    c1 = make_float2(u1.x - u3.y, u1.y + u3.x);
    c2 = f2sub(u0, u2);
    c3 = make_float2(u1.x + u3.y, u1.y - u3.x);
}
// inverse q=4096 butterfly, only outputs 0 and q needed
__device__ __forceinline__ void dit4_lo(float2 c0, float2 c1, float2 c2, float2 c3,
                                        const W3& w, float2& o0, float2& o1) {
    float2 a1 = cmulc(c1, w.w1), a2 = cmulc(c2, w.w2), a3 = cmulc(c3, w.w3);
    float2 u0 = f2add(c0, a2), u1 = f2sub(c0, a2);
    float2 u2 = f2add(a1, a3), u3 = f2sub(a1, a3);
    o0 = f2add(u0, u2);
    o1 = make_float2(u1.x - u3.y, u1.y + u3.x);
}

// Fused fwd stages (s, s+1): radix-16 pass.
template <int LQ>
__device__ __forceinline__ void fwd16_pass(float2* s) {
    const int Q = 1 << LQ;
    const int TWS1 = N_FFT >> (LQ + 4);
    const int TWS2 = N_FFT >> (LQ + 2);
#pragma unroll
    for (int gg = 0; gg < 2; ++gg) {
        const int G = threadIdx.x + gg * THREADS;
        const int j = G & (Q - 1);
        const int base = (G >> LQ) << (LQ + 4);
        float2 e[16];
#pragma unroll
        for (int u = 0; u < 16; ++u) e[u] = s[SWZ(base + j + (u << LQ))];
#pragma unroll
        for (int c = 0; c < 4; ++c) {
            W3 w = loadw((j + (c << LQ)) * TWS1);
            dif4w(e[c], e[c + 4], e[c + 8], e[c + 12], w);
        }
        W3 wB = loadw(j * TWS2);
#pragma unroll
        for (int c = 0; c < 4; ++c)
            dif4w(e[4 * c], e[4 * c + 1], e[4 * c + 2], e[4 * c + 3], wB);
#pragma unroll
        for (int u = 0; u < 16; ++u) s[SWZ(base + j + (u << LQ))] = e[u];
    }
}

// Fused inverse stages (t, t+1): radix-16 pass.
template <int LQ>
__device__ __forceinline__ void inv16_pass(float2* s) {
    const int Q = 1 << LQ;
    const int TWSA = N_FFT >> (LQ + 2);
    const int TWSB = N_FFT >> (LQ + 4);
#pragma unroll
    for (int gg = 0; gg < 2; ++gg) {
        const int G = threadIdx.x + gg * THREADS;
        const int j = G & (Q - 1);
        const int base = (G >> LQ) << (LQ + 4);
        float2 e[16];
#pragma unroll
        for (int u = 0; u < 16; ++u) e[u] = s[SWZ(base + j + (u << LQ))];
        W3 wA = loadw(j * TWSA);
#pragma unroll
        for (int c = 0; c < 4; ++c)
            dit4w(e[4 * c], e[4 * c + 1], e[4 * c + 2], e[4 * c + 3], wA);
#pragma unroll
        for (int c = 0; c < 4; ++c) {
            W3 wB = loadw((j + (c << LQ)) * TWSB);
            dit4w(e[c], e[c + 4], e[c + 8], e[c + 12], wB);
        }
#pragma unroll
        for (int u = 0; u < 16; ++u) s[SWZ(base + j + (u << LQ))] = e[u];
    }
}

// fwd stages 5 (q=4) and 6 (q=1, twiddle-free) on 16 consecutive elems
__device__ __forceinline__ void fwd_tail(float2 e[16]) {
#pragma unroll
    for (int c = 0; c < 4; ++c) {
        W3 w = loadw(c << 10);
        dif4w(e[c], e[c + 4], e[c + 8], e[c + 12], w);
    }
#pragma unroll
    for (int c = 0; c < 4; ++c)
        dif4_nt(e[4 * c], e[4 * c + 1], e[4 * c + 2], e[4 * c + 3]);
}
// inverse stages 0 (twiddle-free) and 1 (q=4)
__device__ __forceinline__ void inv_head(float2 e[16]) {
#pragma unroll
    for (int c = 0; c < 4; ++c)
        dit4_nt(e[4 * c], e[4 * c + 1], e[4 * c + 2], e[4 * c + 3]);
#pragma unroll
    for (int c = 0; c < 4; ++c) {
        W3 w = loadw(c << 10);
        dit4w(e[c], e[c + 4], e[c + 8], e[c + 12], w);
    }
}

// ---------------- fused kernel: bids [0,1024) produce Hf rows; rest consume
__global__ __launch_bounds__(THREADS, 1) void fftconv_kernel(const float* __restrict__ h,
                                                             const float* __restrict__ x,
                                                             const float* __restrict__ Bp,
                                                             float* __restrict__ y) {
    extern __shared__ float2 s[];
    const int bid = blockIdx.x;
    const int tid = threadIdx.x;

    if (bid < D_DIM) {
        // ============ producer: spectrum of (h + B*delta0)/N ============
        const int d = bid;
        const float* hr = h + (size_t)d * L_SIG;
        const float Bv = Bp[d];
        // fwd stage 0 (q=4096), upper half zero-padded, real input
#pragma unroll
        for (int k = 0; k < 8; ++k) {
            int j = tid + THREADS * k;
            float a0r = hr[j] + ((j == 0) ? Bv : 0.f);   // fold B*x into the filter
            float a1r = hr[j + 4096];
            W3 w = loadw(j);
            float2 b0 = make_float2(a0r + a1r, 0.f);
            float2 b2 = make_float2(a0r - a1r, 0.f);
            float2 b1 = make_float2(a0r, -a1r);          // a0 - i*a1 (real inputs)
            float2 b3 = make_float2(a0r,  a1r);          // a0 + i*a1
            s[SWZ(j)]         = b0;
            s[SWZ(j + 4096)]  = cmul(b1, w.w1);
            s[SWZ(j + 8192)]  = cmul(b2, w.w2);
            s[SWZ(j + 12288)] = cmul(b3, w.w3);
        }
        __syncthreads();
        fwd16_pass<8>(s);   // stages 1,2
        __syncthreads();
        fwd16_pass<4>(s);   // stages 3,4
        __syncthreads();
        // stages 5,6 + 1/N scale + store Hf (sector-coalesced)
        const float scale = 1.0f / (float)N_FFT;
        float4* out4 = reinterpret_cast<float4*>(d_Hf4 + ((size_t)d * N_FFT) / 2);
#pragma unroll
        for (int gg = 0; gg < 2; ++gg) {
            const int G = tid + THREADS * gg;
            const int base = G << 4;
            const int r = G & 15;
            float2 e[16];
#pragma unroll
            for (int u = 0; u < 16; ++u) e[u] = s[base + (u ^ r)];
            fwd_tail(e);
#pragma unroll
            for (int v = 0; v < 8; ++v)
                out4[(base >> 1) + v] = make_float4(e[2 * v].x * scale, e[2 * v].y * scale,
                                                    e[2 * v + 1].x * scale, e[2 * v + 1].y * scale);
        }
        __syncthreads();          // all Hf stores issued
        if (tid == 0) {
            __threadfence();      // release
            atomicExch(&d_flags[d], 1u);
        }
    } else {
        // ============ consumer: batch-packed conv ============
        const int c = bid - D_DIM;
        const int d = c >> 1;       // pair-siblings adjacent -> Hf L2 reuse
        const int p = c & 1;
        const float* x0 = x + ((size_t)(2 * p) * D_DIM + d) * L_SIG;
        const float* x1 = x + ((size_t)(2 * p + 1) * D_DIM + d) * L_SIG;
        float* y0       = y + ((size_t)(2 * p) * D_DIM + d) * L_SIG;
        float* y1       = y + ((size_t)(2 * p + 1) * D_DIM + d) * L_SIG;

        // P0: fwd stage 0 straight from global (z = x0 + i*x1), zero-padded
#pragma unroll
        for (int k = 0; k < 8; ++k) {
            int j = tid + THREADS * k;
            float2 a0 = make_float2(x0[j], x1[j]);
            float2 a1 = make_float2(x0[j + 4096], x1[j + 4096]);
            W3 w = loadw(j);
            float2 b0 = f2add(a0, a1);
            float2 b2 = f2sub(a0, a1);
            float2 b1 = make_float2(a0.x + a1.y, a0.y - a1.x);
            float2 b3 = make_float2(a0.x - a1.y, a0.y + a1.x);
            s[SWZ(j)]         = b0;
            s[SWZ(j + 4096)]  = cmul(b1, w.w1);
            s[SWZ(j + 8192)]  = cmul(b2, w.w2);
            s[SWZ(j + 12288)] = cmul(b3, w.w3);
        }
        __syncthreads();
        fwd16_pass<8>(s);   // fwd stages 1,2
        __syncthreads();
        fwd16_pass<4>(s);   // fwd stages 3,4

        // Wait for Hf row d (producers have strictly lower bids -> guaranteed progress)
        if (tid == 0) {
            while (atomicAdd(&d_flags[d], 0u) == 0u) __nanosleep(64);
        }
        __syncthreads();
        __threadfence();          // acquire for Hf reads below

        // P3: fwd stages 5,6 + pointwise Hf (pre-scaled) + inv stages 0,1
        const float4* H4 = d_Hf4 + ((size_t)d * N_FFT) / 2;
#pragma unroll
        for (int gg = 0; gg < 2; ++gg) {
            const int G = tid + THREADS * gg;
            const int base = G << 4;
            const int r = G & 15;
            float4 hv[8];
#pragma unroll
            for (int v = 0; v < 8; ++v) hv[v] = H4[(base >> 1) + v];  // prefetch
            float2 e[16];
#pragma unroll
            for (int u = 0; u < 16; ++u) e[u] = s[base + (u ^ r)];
            fwd_tail(e);
#pragma unroll
            for (int v = 0; v < 8; ++v) {
                e[2 * v]     = cmul(e[2 * v],     make_float2(hv[v].x, hv[v].y));
                e[2 * v + 1] = cmul(e[2 * v + 1], make_float2(hv[v].z, hv[v].w));
            }
            inv_head(e);
#pragma unroll
            for (int u = 0; u < 16; ++u) s[base + (u ^ r)] = e[u];
        }
        __syncthreads();
        inv16_pass<4>(s);   // inv stages 2,3
        __syncthreads();
        inv16_pass<8>(s);   // inv stages 4,5
        __syncthreads();

        // P6: inv stage 6 (q=4096) + y store, upper garbage outputs never computed
#pragma unroll
        for (int k = 0; k < 8; ++k) {
            int j = tid + THREADS * k;
            float2 c0 = s[SWZ(j)];
            float2 c1 = s[SWZ(j + 4096)];
            float2 c2 = s[SWZ(j + 8192)];
            float2 c3 = s[SWZ(j + 12288)];
            W3 w = loadw(j);
            float2 o0, o1;
            dit4_lo(c0, c1, c2, c3, w, o0, o1);
            y0[j]        = o0.x;
            y1[j]        = o0.y;
            y0[j + 4096] = o1.x;
            y1[j + 4096] = o1.y;
        }
    }
}

extern "C" void kernel_launch(void* const* d_in, const int* in_sizes, int n_in,
                              void* d_out, int out_size) {
    const float* h = (const float*)d_in[0];
    const float* x = (const float*)d_in[1];
    const float* B = (const float*)d_in[2];
    float* y = (float*)d_out;

    const size_t smem = (size_t)N_FFT * sizeof(float2);  // 131072 B
    cudaFuncSetAttribute(fftconv_kernel, cudaFuncAttributeMaxDynamicSharedMemorySize, (int)smem);

    init_kernel<<<48, 256>>>();
    fftconv_kernel<<<D_DIM + D_DIM * (BSZ / 2), THREADS, smem>>>(h, x, B, y);
}

// round 17
// speedup vs baseline: 1.3831x; 1.3831x over previous
#include <cuda_runtime.h>
#include <math.h>

#define N_FFT   16384
#define L_SIG   8192
#define D_DIM   1024
#define BSZ     4
#define THREADS 512

// XOR bank swizzle (Round-4 layout): <=2-way for all strides used here.
#define SWZ(i) ((i) ^ (((i) >> 4) & 15))

__device__ float2 d_tw[N_FFT / 4];                   // exp(-2*pi*i*k/N), k < N/4
__device__ float4 d_Hf4[(size_t)D_DIM * N_FFT / 2];  // spectra of (h + B*delta0)/N
__device__ unsigned d_flags[D_DIM];

__global__ void init_kernel() {
    int k = blockIdx.x * blockDim.x + threadIdx.x;
    if (k < N_FFT / 4) {
        double ang = -2.0 * 3.14159265358979323846 * (double)k / (double)N_FFT;
        d_tw[k] = make_float2((float)cos(ang), (float)sin(ang));
    }
    if (k < D_DIM) d_flags[k] = 0u;
}

__device__ __forceinline__ float2 f2add(float2 a, float2 b) {
    return make_float2(a.x + b.x, a.y + b.y);
}
__device__ __forceinline__ float2 f2sub(float2 a, float2 b) {
    return make_float2(a.x - b.x, a.y - b.y);
}
__device__ __forceinline__ float2 cmul(float2 a, float2 b) {
    return make_float2(a.x * b.x - a.y * b.y, a.x * b.y + a.y * b.x);
}
// multiply by conj(b): inverse butterflies use unconjugated powers directly
__device__ __forceinline__ float2 cmulc(float2 a, float2 b) {
    return make_float2(a.x * b.x + a.y * b.y, a.y * b.x - a.x * b.y);
}

// One table load (w1), two in-register powers — computed ONCE per distinct twiddle.
struct W3 { float2 w1, w2, w3; };
__device__ __forceinline__ W3 mkw3(float2 w1) {
    W3 w;
    w.w1 = w1;
    w.w2 = cmul(w1, w1);
    w.w3 = cmul(w1, w.w2);
    return w;
}

// DIF radix-4 butterfly, precomputed twiddle powers on outputs
__device__ __forceinline__ void dif4w(float2& a0, float2& a1, float2& a2, float2& a3,
                                      const W3& w) {
    float2 t0 = f2add(a0, a2), t1 = f2sub(a0, a2);
    float2 t2 = f2add(a1, a3), t3 = f2sub(a1, a3);
    float2 b0 = f2add(t0, t2), b2 = f2sub(t0, t2);
    float2 b1 = make_float2(t1.x + t3.y, t1.y - t3.x);   // t1 - i*t3
    float2 b3 = make_float2(t1.x - t3.y, t1.y + t3.x);   // t1 + i*t3
    a0 = b0; a1 = cmul(b1, w.w1); a2 = cmul(b2, w.w2); a3 = cmul(b3, w.w3);
}
__device__ __forceinline__ void dif4_nt(float2& a0, float2& a1, float2& a2, float2& a3) {
    float2 t0 = f2add(a0, a2), t1 = f2sub(a0, a2);
    float2 t2 = f2add(a1, a3), t3 = f2sub(a1, a3);
    a0 = f2add(t0, t2);
    a2 = f2sub(t0, t2);
    a1 = make_float2(t1.x + t3.y, t1.y - t3.x);
    a3 = make_float2(t1.x - t3.y, t1.y + t3.x);
}

// DIT radix-4 inverse butterfly, conj applied via cmulc (no negations anywhere)
__device__ __forceinline__ void dit4w(float2& c0, float2& c1, float2& c2, float2& c3,
                                      const W3& w) {
    float2 a1 = cmulc(c1, w.w1), a2 = cmulc(c2, w.w2), a3 = cmulc(c3, w.w3);
    float2 u0 = f2add(c0, a2), u1 = f2sub(c0, a2);
    float2 u2 = f2add(a1, a3), u3 = f2sub(a1, a3);
    c0 = f2add(u0, u2);
    c1 = make_float2(u1.x - u3.y, u1.y + u3.x);  // u1 + i*u3
    c2 = f2sub(u0, u2);
    c3 = make_float2(u1.x + u3.y, u1.y - u3.x);  // u1 - i*u3
}
__device__ __forceinline__ void dit4_nt(float2& c0, float2& c1, float2& c2, float2& c3) {
    float2 u0 = f2add(c0, c2), u1 = f2sub(c0, c2);
    float2 u2 = f2add(c1, c3), u3 = f2sub(c1, c3);
    c0 = f2add(u0, u2);
    c1 = make_float2(u1.x - u3.y, u1.y + u3.x);
    c2 = f2sub(u0, u2);
    c3 = make_float2(u1.x + u3.y, u1.y - u3.x);
}
// inverse q=4096 butterfly, only outputs 0 and q needed
__device__ __forceinline__ void dit4_lo(float2 c0, float2 c1, float2 c2, float2 c3,
                                        const W3& w, float2& o0, float2& o1) {
    float2 a1 = cmulc(c1, w.w1), a2 = cmulc(c2, w.w2), a3 = cmulc(c3, w.w3);
    float2 u0 = f2add(c0, a2), u1 = f2sub(c0, a2);
    float2 u2 = f2add(a1, a3), u3 = f2sub(a1, a3);
    o0 = f2add(u0, u2);
    o1 = make_float2(u1.x - u3.y, u1.y + u3.x);
}

// Fused fwd stages (s, s+1): radix-16 pass.
template <int LQ>
__device__ __forceinline__ void fwd16_pass(float2* s) {
    const int Q = 1 << LQ;
    const int TWS1 = N_FFT >> (LQ + 4);
    const int TWS2 = N_FFT >> (LQ + 2);
#pragma unroll
    for (int gg = 0; gg < 2; ++gg) {
        const int G = threadIdx.x + gg * THREADS;
        const int j = G & (Q - 1);
        const int base = (G >> LQ) << (LQ + 4);
        float2 e[16];
#pragma unroll
        for (int u = 0; u < 16; ++u) e[u] = s[SWZ(base + j + (u << LQ))];
#pragma unroll
        for (int c = 0; c < 4; ++c) {
            W3 w = mkw3(d_tw[(j + (c << LQ)) * TWS1]);
            dif4w(e[c], e[c + 4], e[c + 8], e[c + 12], w);
        }
        W3 wB = mkw3(d_tw[j * TWS2]);   // powers computed once, used by 4 butterflies
#pragma unroll
        for (int c = 0; c < 4; ++c)
            dif4w(e[4 * c], e[4 * c + 1], e[4 * c + 2], e[4 * c + 3], wB);
#pragma unroll
        for (int u = 0; u < 16; ++u) s[SWZ(base + j + (u << LQ))] = e[u];
    }
}

// Fused inverse stages (t, t+1): radix-16 pass.
template <int LQ>
__device__ __forceinline__ void inv16_pass(float2* s) {
    const int Q = 1 << LQ;
    const int TWSA = N_FFT >> (LQ + 2);
    const int TWSB = N_FFT >> (LQ + 4);
#pragma unroll
    for (int gg = 0; gg < 2; ++gg) {
        const int G = threadIdx.x + gg * THREADS;
        const int j = G & (Q - 1);
        const int base = (G >> LQ) << (LQ + 4);
        float2 e[16];
#pragma unroll
        for (int u = 0; u < 16; ++u) e[u] = s[SWZ(base + j + (u << LQ))];
        W3 wA = mkw3(d_tw[j * TWSA]);   // powers computed once, used by 4 butterflies
#pragma unroll
        for (int c = 0; c < 4; ++c)
            dit4w(e[4 * c], e[4 * c + 1], e[4 * c + 2], e[4 * c + 3], wA);
#pragma unroll
        for (int c = 0; c < 4; ++c) {
            W3 wB = mkw3(d_tw[(j + (c << LQ)) * TWSB]);
            dit4w(e[c], e[c + 4], e[c + 8], e[c + 12], wB);
        }
#pragma unroll
        for (int u = 0; u < 16; ++u) s[SWZ(base + j + (u << LQ))] = e[u];
    }
}

// fwd stages 5 (q=4) and 6 (q=1, twiddle-free) on 16 consecutive elems
__device__ __forceinline__ void fwd_tail(float2 e[16]) {
#pragma unroll
    for (int c = 0; c < 4; ++c) {
        W3 w = mkw3(d_tw[c << 10]);
        dif4w(e[c], e[c + 4], e[c + 8], e[c + 12], w);
    }
#pragma unroll
    for (int c = 0; c < 4; ++c)
        dif4_nt(e[4 * c], e[4 * c + 1], e[4 * c + 2], e[4 * c + 3]);
}
// inverse stages 0 (twiddle-free) and 1 (q=4)
__device__ __forceinline__ void inv_head(float2 e[16]) {
#pragma unroll
    for (int c = 0; c < 4; ++c)
        dit4_nt(e[4 * c], e[4 * c + 1], e[4 * c + 2], e[4 * c + 3]);
#pragma unroll
    for (int c = 0; c < 4; ++c) {
        W3 w = mkw3(d_tw[c << 10]);
        dit4w(e[c], e[c + 4], e[c + 8], e[c + 12], w);
    }
}

// ---------------- fused kernel: bids [0,1024) produce Hf rows; rest consume
__global__ __launch_bounds__(THREADS, 1) void fftconv_kernel(const float* __restrict__ h,
                                                             const float* __restrict__ x,
                                                             const float* __restrict__ Bp,
                                                             float* __restrict__ y) {
    extern __shared__ float2 s[];
    const int bid = blockIdx.x;
    const int tid = threadIdx.x;

    if (bid < D_DIM) {
        // ============ producer: spectrum of (h + B*delta0)/N ============
        const int d = bid;
        const float* hr = h + (size_t)d * L_SIG;
        const float Bv = Bp[d];
        // fwd stage 0 (q=4096), upper half zero-padded, real input
#pragma unroll
        for (int k = 0; k < 8; ++k) {
            int j = tid + THREADS * k;
            float a0r = hr[j] + ((j == 0) ? Bv : 0.f);   // fold B*x into the filter
            float a1r = hr[j + 4096];
            W3 w = mkw3(d_tw[j]);
            float2 b0 = make_float2(a0r + a1r, 0.f);
            float2 b2 = make_float2(a0r - a1r, 0.f);
            float2 b1 = make_float2(a0r, -a1r);          // a0 - i*a1 (real inputs)
            float2 b3 = make_float2(a0r,  a1r);          // a0 + i*a1
            s[SWZ(j)]         = b0;
            s[SWZ(j + 4096)]  = cmul(b1, w.w1);
            s[SWZ(j + 8192)]  = cmul(b2, w.w2);
            s[SWZ(j + 12288)] = cmul(b3, w.w3);
        }
        __syncthreads();
        fwd16_pass<8>(s);   // stages 1,2
        __syncthreads();
        fwd16_pass<4>(s);   // stages 3,4
        __syncthreads();
        // stages 5,6 + 1/N scale + store Hf (sector-coalesced)
        const float scale = 1.0f / (float)N_FFT;
        float4* out4 = reinterpret_cast<float4*>(d_Hf4 + ((size_t)d * N_FFT) / 2);
#pragma unroll
        for (int gg = 0; gg < 2; ++gg) {
            const int G = tid + THREADS * gg;
            const int base = G << 4;
            const int r = G & 15;
            float2 e[16];
#pragma unroll
            for (int u = 0; u < 16; ++u) e[u] = s[base + (u ^ r)];
            fwd_tail(e);
#pragma unroll
            for (int v = 0; v < 8; ++v)
                out4[(base >> 1) + v] = make_float4(e[2 * v].x * scale, e[2 * v].y * scale,
                                                    e[2 * v + 1].x * scale, e[2 * v + 1].y * scale);
        }
        __syncthreads();          // all Hf stores issued
        if (tid == 0) {
            __threadfence();      // release
            atomicExch(&d_flags[d], 1u);
        }
    } else {
        // ============ consumer: batch-packed conv ============
        const int c = bid - D_DIM;
        const int d = c >> 1;       // pair-siblings adjacent -> Hf L2 reuse
        const int p = c & 1;
        const float* x0 = x + ((size_t)(2 * p) * D_DIM + d) * L_SIG;
        const float* x1 = x + ((size_t)(2 * p + 1) * D_DIM + d) * L_SIG;
        float* y0       = y + ((size_t)(2 * p) * D_DIM + d) * L_SIG;
        float* y1       = y + ((size_t)(2 * p + 1) * D_DIM + d) * L_SIG;

        // P0: fwd stage 0 straight from global (z = x0 + i*x1), zero-padded
#pragma unroll
        for (int k = 0; k < 8; ++k) {
            int j = tid + THREADS * k;
            float2 a0 = make_float2(x0[j], x1[j]);
            float2 a1 = make_float2(x0[j + 4096], x1[j + 4096]);
            W3 w = mkw3(d_tw[j]);
            float2 b0 = f2add(a0, a1);
            float2 b2 = f2sub(a0, a1);
            float2 b1 = make_float2(a0.x + a1.y, a0.y - a1.x);
            float2 b3 = make_float2(a0.x - a1.y, a0.y + a1.x);
            s[SWZ(j)]         = b0;
            s[SWZ(j + 4096)]  = cmul(b1, w.w1);
            s[SWZ(j + 8192)]  = cmul(b2, w.w2);
            s[SWZ(j + 12288)] = cmul(b3, w.w3);
        }
        __syncthreads();
        fwd16_pass<8>(s);   // fwd stages 1,2
        __syncthreads();
        fwd16_pass<4>(s);   // fwd stages 3,4

        // Wait for Hf row d (producers have strictly lower bids -> guaranteed progress)
        if (tid == 0) {
            while (atomicAdd(&d_flags[d], 0u) == 0u) __nanosleep(64);
        }
        __syncthreads();
        __threadfence();          // acquire for Hf reads below

        // P3: fwd stages 5,6 + pointwise Hf (pre-scaled) + inv stages 0,1
        const float4* H4 = d_Hf4 + ((size_t)d * N_FFT) / 2;
#pragma unroll
        for (int gg = 0; gg < 2; ++gg) {
            const int G = tid + THREADS * gg;
            const int base = G << 4;
            const int r = G & 15;
            float4 hv[8];
#pragma unroll
            for (int v = 0; v < 8; ++v) hv[v] = H4[(base >> 1) + v];  // prefetch
            float2 e[16];
#pragma unroll
            for (int u = 0; u < 16; ++u) e[u] = s[base + (u ^ r)];
            fwd_tail(e);
#pragma unroll
            for (int v = 0; v < 8; ++v) {
                e[2 * v]     = cmul(e[2 * v],     make_float2(hv[v].x, hv[v].y));
                e[2 * v + 1] = cmul(e[2 * v + 1], make_float2(hv[v].z, hv[v].w));
            }
            inv_head(e);
#pragma unroll
            for (int u = 0; u < 16; ++u) s[base + (u ^ r)] = e[u];
        }
        __syncthreads();
        inv16_pass<4>(s);   // inv stages 2,3
        __syncthreads();
        inv16_pass<8>(s);   // inv stages 4,5
        __syncthreads();

        // P6: inv stage 6 (q=4096) + y store, upper garbage outputs never computed
#pragma unroll
        for (int k = 0; k < 8; ++k) {
            int j = tid + THREADS * k;
            float2 c0 = s[SWZ(j)];
            float2 c1 = s[SWZ(j + 4096)];
            float2 c2 = s[SWZ(j + 8192)];
            float2 c3 = s[SWZ(j + 12288)];
            W3 w = mkw3(d_tw[j]);
            float2 o0, o1;
            dit4_lo(c0, c1, c2, c3, w, o0, o1);
            y0[j]        = o0.x;
            y1[j]        = o0.y;
            y0[j + 4096] = o1.x;
            y1[j + 4096] = o1.y;
        }
    }
}

extern "C" void kernel_launch(void* const* d_in, const int* in_sizes, int n_in,
                              void* d_out, int out_size) {
    const float* h = (const float*)d_in[0];
    const float* x = (const float*)d_in[1];
    const float* B = (const float*)d_in[2];
    float* y = (float*)d_out;

    const size_t smem = (size_t)N_FFT * sizeof(float2);  // 131072 B
    cudaFuncSetAttribute(fftconv_kernel, cudaFuncAttributeMaxDynamicSharedMemorySize, (int)smem);

    init_kernel<<<16, 256>>>();
    fftconv_kernel<<<D_DIM + D_DIM * (BSZ / 2), THREADS, smem>>>(h, x, B, y);
}